// round 1
// baseline (speedup 1.0000x reference)
#include <cuda_runtime.h>
#include <cstdint>

// Problem constants
#define NB   32
#define TB   4096
#define DD   256
#define NQ   4
#define KK   1024
#define NTOT (NB*TB)          // 131072 rows

// Tiling
#define BM   128              // rows per block
#define BNC  128              // codes per chunk
#define BK   32               // d per staging chunk
#define NTHREADS 256

// Scratch (device globals are the allowed scratch mechanism)
__device__ float g_resT[(size_t)DD * NTOT];     // residual, transposed [d][n]  (134 MB)
__device__ float g_cbT[(size_t)NQ * DD * KK];   // codebooks transposed [s][d][k] (4 MB)
__device__ float g_c2[NQ * KK];                 // ||c||^2 per code

// ---------------- packed f32x2 helpers ----------------
__device__ __forceinline__ unsigned long long pack2(float x) {
    unsigned long long r;
    unsigned int xi = __float_as_uint(x);
    asm("mov.b64 %0, {%1, %1};" : "=l"(r) : "r"(xi));
    return r;
}
__device__ __forceinline__ void ffma2(unsigned long long &acc,
                                      unsigned long long a,
                                      unsigned long long b) {
    asm("fma.rn.f32x2 %0, %1, %2, %0;" : "+l"(acc) : "l"(a), "l"(b));
}
__device__ __forceinline__ float2 unpack2(unsigned long long v) {
    unsigned int lo, hi;
    asm("mov.b64 {%0, %1}, %2;" : "=r"(lo), "=r"(hi) : "l"(v));
    return make_float2(__uint_as_float(lo), __uint_as_float(hi));
}

// ---------------- generic 32x32 tiled transpose: src[R][C] -> dst[C][R] ----------------
__global__ void transpose_k(const float* __restrict__ src, float* __restrict__ dst,
                            int R, int C, long srcBatch, long dstBatch) {
    __shared__ float tile[32][33];
    const float* s = src + (long)blockIdx.z * srcBatch;
    float*       d = dst + (long)blockIdx.z * dstBatch;
    int c0 = blockIdx.x * 32, r0 = blockIdx.y * 32;
    int tx = threadIdx.x, ty = threadIdx.y;           // 32 x 8
    #pragma unroll
    for (int i = 0; i < 32; i += 8)
        tile[ty + i][tx] = s[(long)(r0 + ty + i) * C + c0 + tx];
    __syncthreads();
    #pragma unroll
    for (int i = 0; i < 32; i += 8)
        d[(long)(c0 + ty + i) * R + r0 + tx] = tile[tx][ty + i];
}

// ---------------- ||c||^2 per code (one warp per code) ----------------
__global__ void c2_k(const float* __restrict__ cb) {
    int w = (blockIdx.x * blockDim.x + threadIdx.x) >> 5;   // global code id over NQ*KK
    int lane = threadIdx.x & 31;
    if (w >= NQ * KK) return;
    const float* row = cb + (long)w * DD;
    float s = 0.f;
    #pragma unroll
    for (int j = lane; j < DD; j += 32) { float v = row[j]; s = fmaf(v, v, s); }
    #pragma unroll
    for (int o = 16; o; o >>= 1) s += __shfl_xor_sync(0xffffffffu, s, o);
    if (lane == 0) g_c2[w] = s;
}

// ---------------- main per-stage kernel: argmin over K + residual update ----------------
__global__ void __launch_bounds__(NTHREADS, 1)
rvq_stage_k(int s, float* __restrict__ outCodes, int writeCodes) {
    extern __shared__ float sm[];
    float* Rs       = sm;                          // [256][128]  residual tile (transposed)
    float* Bs       = Rs + DD * BM;                // [32][128]   codebook chunk (transposed)
    float* c2s      = Bs + BK * BNC;               // [128]
    float* red_d    = c2s + BNC;                   // [128][16]
    int*   red_c    = (int*)(red_d + BM * 16);     // [128][16]
    int*   codes_sm = red_c + BM * 16;             // [128]

    const int t  = threadIdx.x;
    const int tx = t & 15, ty = t >> 4;
    const long rowBase = (long)blockIdx.x * BM;

    const float* cbT = g_cbT + (size_t)s * DD * KK;
    const float* c2p = g_c2 + s * KK;

    // Load residual tile: Rs[d][r] = g_resT[d][rowBase + r]   (coalesced, conflict-free)
    for (int i4 = t; i4 < DD * (BM / 4); i4 += NTHREADS) {
        int d = i4 >> 5, r4 = i4 & 31;
        float4 v = *(const float4*)&g_resT[(size_t)d * NTOT + rowBase + r4 * 4];
        *(float4*)&Rs[d * BM + r4 * 4] = v;
    }

    float bestd[8];
    int   bestc[8];
    #pragma unroll
    for (int i = 0; i < 8; i++) { bestd[i] = 3.4e38f; bestc[i] = 0; }

    for (int cc = 0; cc < KK / BNC; cc++) {
        unsigned long long acc[8][4];
        #pragma unroll
        for (int m = 0; m < 8; m++)
            #pragma unroll
            for (int p = 0; p < 4; p++) acc[m][p] = 0ull;

        for (int dk = 0; dk < DD / BK; dk++) {
            __syncthreads();
            // Stage Bs[dd][c] = cbT[dk*BK+dd][cc*128 + c]   (coalesced, conflict-free)
            for (int i4 = t; i4 < BK * (BNC / 4); i4 += NTHREADS) {
                int dd = i4 >> 5, c4 = i4 & 31;
                float4 v = *(const float4*)&cbT[(size_t)(dk * BK + dd) * KK + cc * BNC + c4 * 4];
                *(float4*)&Bs[dd * BNC + c4 * 4] = v;
            }
            if (dk == 0 && t < BNC) c2s[t] = c2p[cc * BNC + t];
            __syncthreads();

            #pragma unroll 4
            for (int dd = 0; dd < BK; dd++) {
                const float4 a0 = *(const float4*)&Rs[(dk * BK + dd) * BM + ty * 4];
                const float4 a1 = *(const float4*)&Rs[(dk * BK + dd) * BM + 64 + ty * 4];
                const ulonglong2 b0 = *(const ulonglong2*)&Bs[dd * BNC + tx * 4];
                const ulonglong2 b1 = *(const ulonglong2*)&Bs[dd * BNC + 64 + tx * 4];
                unsigned long long A[8];
                A[0] = pack2(a0.x); A[1] = pack2(a0.y); A[2] = pack2(a0.z); A[3] = pack2(a0.w);
                A[4] = pack2(a1.x); A[5] = pack2(a1.y); A[6] = pack2(a1.z); A[7] = pack2(a1.w);
                #pragma unroll
                for (int m = 0; m < 8; m++) {
                    ffma2(acc[m][0], A[m], b0.x);
                    ffma2(acc[m][1], A[m], b0.y);
                    ffma2(acc[m][2], A[m], b1.x);
                    ffma2(acc[m][3], A[m], b1.y);
                }
            }
        }

        // Chunk epilogue: dist = c2 - 2*dot ; lexicographic argmin (first-min on ties)
        #pragma unroll
        for (int m = 0; m < 8; m++) {
            #pragma unroll
            for (int p = 0; p < 4; p++) {
                float2 dv = unpack2(acc[m][p]);
                int cl = (p < 2) ? (tx * 4 + 2 * p) : (64 + tx * 4 + 2 * (p - 2));
                float d0 = fmaf(-2.f, dv.x, c2s[cl]);
                float d1 = fmaf(-2.f, dv.y, c2s[cl + 1]);
                int cg0 = cc * BNC + cl;
                if (d0 < bestd[m] || (d0 == bestd[m] && cg0 < bestc[m])) { bestd[m] = d0; bestc[m] = cg0; }
                if (d1 < bestd[m] || (d1 == bestd[m] && cg0 + 1 < bestc[m])) { bestd[m] = d1; bestc[m] = cg0 + 1; }
            }
        }
    }

    // Cross-thread argmin reduction (16 threads share each row)
    __syncthreads();
    #pragma unroll
    for (int m = 0; m < 8; m++) {
        int rloc = (m < 4) ? (ty * 4 + m) : (64 + ty * 4 + (m - 4));
        red_d[rloc * 16 + tx] = bestd[m];
        red_c[rloc * 16 + tx] = bestc[m];
    }
    __syncthreads();
    if (t < BM) {
        float bd = red_d[t * 16];
        int   bc = red_c[t * 16];
        #pragma unroll
        for (int j = 1; j < 16; j++) {
            float d = red_d[t * 16 + j];
            int   c = red_c[t * 16 + j];
            if (d < bd || (d == bd && c < bc)) { bd = d; bc = c; }
        }
        codes_sm[t] = bc;
        if (writeCodes) outCodes[(rowBase + t) * NQ + s] = (float)bc;
    }
    __syncthreads();

    // Residual update: g_resT[d][rowBase+r] = Rs[d][r] - cbT[d][code_r]
    for (int i = t; i < DD * BM; i += NTHREADS) {
        int d = i >> 7, r = i & 127;
        int code = codes_sm[r];
        g_resT[(size_t)d * NTOT + rowBase + r] = Rs[d * BM + r] - cbT[(size_t)d * KK + code];
    }
}

// ---------------- finalize: quantised[n][d] = x[n][d] - resT[d][n] ----------------
__global__ void finalize_k(const float* __restrict__ x, float* __restrict__ out) {
    __shared__ float tile[32][33];
    int n0 = blockIdx.x * 32, d0 = blockIdx.y * 32;
    int tx = threadIdx.x, ty = threadIdx.y;   // 32 x 8
    #pragma unroll
    for (int i = 0; i < 32; i += 8)
        tile[ty + i][tx] = g_resT[(size_t)(d0 + ty + i) * NTOT + n0 + tx];
    __syncthreads();
    #pragma unroll
    for (int i = 0; i < 32; i += 8) {
        long n = n0 + ty + i;
        int  d = d0 + tx;
        out[n * DD + d] = x[n * DD + d] - tile[tx][ty + i];
    }
}

// ---------------- launch ----------------
extern "C" void kernel_launch(void* const* d_in, const int* in_sizes, int n_in,
                              void* d_out, int out_size) {
    const float* x  = (const float*)d_in[0];
    const float* cb = (const float*)d_in[1];
    float* out = (float*)d_out;

    const long QE = (long)NTOT * DD;               // 33554432
    const long CE = (long)NTOT * NQ;               // 524288

    int writeQ = (out_size >= QE) ? 1 : 0;
    float* outCodes = nullptr;
    int writeCodes = 0;
    if ((long)out_size >= QE + CE) { outCodes = out + QE; writeCodes = 1; }
    else if (!writeQ && (long)out_size >= CE) { outCodes = out; writeCodes = 1; }

    // SMEM size for the stage kernel
    const int SMEM = (DD * BM + BK * BNC + BNC + BM * 16) * 4 + BM * 16 * 4 + BM * 4;
    cudaFuncSetAttribute(rvq_stage_k, cudaFuncAttributeMaxDynamicSharedMemorySize, SMEM);

    float* cbT_ptr = nullptr;
    cudaGetSymbolAddress((void**)&cbT_ptr, g_cbT);
    float* resT_ptr = nullptr;
    cudaGetSymbolAddress((void**)&resT_ptr, g_resT);

    dim3 tb(32, 8);
    // codebooks [NQ][K][D] -> [NQ][D][K]
    transpose_k<<<dim3(DD / 32, KK / 32, NQ), tb>>>(cb, cbT_ptr, KK, DD,
                                                    (long)KK * DD, (long)DD * KK);
    // x [N][D] -> resT [D][N]
    transpose_k<<<dim3(DD / 32, NTOT / 32, 1), tb>>>(x, resT_ptr, NTOT, DD, 0, 0);
    // ||c||^2
    c2_k<<<(NQ * KK * 32 + 255) / 256, 256>>>(cb);

    for (int s = 0; s < NQ; s++)
        rvq_stage_k<<<NTOT / BM, NTHREADS, SMEM>>>(s, outCodes, writeCodes);

    if (writeQ)
        finalize_k<<<dim3(NTOT / 32, DD / 32), tb>>>(x, out);
}

// round 2
// speedup vs baseline: 1.3881x; 1.3881x over previous
#include <cuda_runtime.h>
#include <cstdint>

// Problem constants
#define NB   32
#define TB   4096
#define DD   256
#define NQ   4
#define KK   1024
#define NTOT (NB*TB)          // 131072 rows

// Tiling
#define BM   64               // rows per block
#define BNC  128              // codes per chunk
#define BK   32               // d per staging chunk
#define NTHREADS 256
#define NCHUNK   (KK/BNC)     // 8 code chunks
#define NDK      (DD/BK)      // 8 d chunks
#define NITER    (NCHUNK*NDK) // 64

// Scratch
__device__ float g_resT[(size_t)DD * NTOT];     // residual, transposed [d][n]
__device__ float g_cbT[(size_t)NQ * DD * KK];   // codebooks transposed [s][d][k]
__device__ float g_c2[NQ * KK];                 // ||c||^2 per code

// ---------------- packed f32x2 helpers ----------------
__device__ __forceinline__ unsigned long long pack2(float x) {
    unsigned long long r;
    unsigned int xi = __float_as_uint(x);
    asm("mov.b64 %0, {%1, %1};" : "=l"(r) : "r"(xi));
    return r;
}
__device__ __forceinline__ void ffma2(unsigned long long &acc,
                                      unsigned long long a,
                                      unsigned long long b) {
    asm("fma.rn.f32x2 %0, %1, %2, %0;" : "+l"(acc) : "l"(a), "l"(b));
}
__device__ __forceinline__ float2 unpack2(unsigned long long v) {
    unsigned int lo, hi;
    asm("mov.b64 {%0, %1}, %2;" : "=r"(lo), "=r"(hi) : "l"(v));
    return make_float2(__uint_as_float(lo), __uint_as_float(hi));
}
__device__ __forceinline__ void cpasync16(uint32_t s, const void* g) {
    asm volatile("cp.async.cg.shared.global [%0], [%1], 16;" :: "r"(s), "l"(g));
}
__device__ __forceinline__ void cpcommit() {
    asm volatile("cp.async.commit_group;" ::: "memory");
}

// ---------------- generic 32x32 tiled transpose: src[R][C] -> dst[C][R] ----------------
__global__ void transpose_k(const float* __restrict__ src, float* __restrict__ dst,
                            int R, int C, long srcBatch, long dstBatch) {
    __shared__ float tile[32][33];
    const float* s = src + (long)blockIdx.z * srcBatch;
    float*       d = dst + (long)blockIdx.z * dstBatch;
    int c0 = blockIdx.x * 32, r0 = blockIdx.y * 32;
    int tx = threadIdx.x, ty = threadIdx.y;           // 32 x 8
    #pragma unroll
    for (int i = 0; i < 32; i += 8)
        tile[ty + i][tx] = s[(long)(r0 + ty + i) * C + c0 + tx];
    __syncthreads();
    #pragma unroll
    for (int i = 0; i < 32; i += 8)
        d[(long)(c0 + ty + i) * R + r0 + tx] = tile[tx][ty + i];
}

// ---------------- ||c||^2 per code (one warp per code) ----------------
__global__ void c2_k(const float* __restrict__ cb) {
    int w = (blockIdx.x * blockDim.x + threadIdx.x) >> 5;
    int lane = threadIdx.x & 31;
    if (w >= NQ * KK) return;
    const float* row = cb + (long)w * DD;
    float s = 0.f;
    #pragma unroll
    for (int j = lane; j < DD; j += 32) { float v = row[j]; s = fmaf(v, v, s); }
    #pragma unroll
    for (int o = 16; o; o >>= 1) s += __shfl_xor_sync(0xffffffffu, s, o);
    if (lane == 0) g_c2[w] = s;
}

// ---------------- main per-stage kernel ----------------
__global__ void __launch_bounds__(NTHREADS, 2)
rvq_stage_k(int s, float* __restrict__ outCodes, int writeCodes) {
    extern __shared__ float sm[];
    float* Rs       = sm;                          // [256][64]  residual tile
    float* Bs       = Rs + DD * BM;                // 3 x [32][128] codebook chunks
    int*   codes_sm = (int*)(Bs + 3 * BK * BNC);   // [64]

    const int t  = threadIdx.x;
    const int tx = t & 15, ty = t >> 4;            // 16 code-cols x 16 row-groups
    const long rowBase = (long)blockIdx.x * BM;

    const float* cbT = g_cbT + (size_t)s * DD * KK;
    const float* c2p = g_c2 + s * KK;

    const uint32_t RsAddr = (uint32_t)__cvta_generic_to_shared(Rs);
    const uint32_t BsAddr = (uint32_t)__cvta_generic_to_shared(Bs);

    // ---- async group 0: residual tile + B chunk 0 ----
    #pragma unroll
    for (int k = 0; k < (DD * BM / 4) / NTHREADS; k++) {       // 16 x 16B
        int i4 = t + k * NTHREADS;                              // [0,4096)
        int d = i4 >> 4, r4 = i4 & 15;
        cpasync16(RsAddr + (d * BM + r4 * 4) * 4,
                  &g_resT[(size_t)d * NTOT + rowBase + r4 * 4]);
    }
    {   // B chunk for iter 0 (cc=0, dk=0) into buffer 0
        #pragma unroll
        for (int k = 0; k < 4; k++) {
            int i4 = t + k * NTHREADS;                          // [0,1024)
            int dd = i4 >> 5, c4 = i4 & 31;
            cpasync16(BsAddr + (dd * BNC + c4 * 4) * 4,
                      &cbT[(size_t)dd * KK + c4 * 4]);
        }
    }
    cpcommit();
    // ---- async group 1: B chunk for iter 1 (cc=0, dk=1) into buffer 1 ----
    {
        #pragma unroll
        for (int k = 0; k < 4; k++) {
            int i4 = t + k * NTHREADS;
            int dd = i4 >> 5, c4 = i4 & 31;
            cpasync16(BsAddr + (BK * BNC + dd * BNC + c4 * 4) * 4,
                      &cbT[(size_t)(BK + dd) * KK + c4 * 4]);
        }
    }
    cpcommit();

    float bestd[4];
    int   bestc[4];
    #pragma unroll
    for (int m = 0; m < 4; m++) { bestd[m] = 3.4e38f; bestc[m] = 0; }

    unsigned long long acc[4][4];

    for (int i = 0; i < NITER; i++) {
        if (i < NITER - 1) asm volatile("cp.async.wait_group 1;" ::: "memory");
        else               asm volatile("cp.async.wait_group 0;" ::: "memory");
        __syncthreads();

        const int cc = i >> 3, dk = i & 7;
        const float* bbuf = Bs + (i % 3) * (BK * BNC);

        if (dk == 0) {
            #pragma unroll
            for (int m = 0; m < 4; m++)
                #pragma unroll
                for (int p = 0; p < 4; p++) acc[m][p] = 0ull;
        }

        #pragma unroll 8
        for (int dd = 0; dd < BK; dd++) {
            const float4 a0 = *(const float4*)&Rs[(dk * BK + dd) * BM + ty * 4];
            const ulonglong2 b0 = *(const ulonglong2*)&bbuf[dd * BNC + tx * 4];
            const ulonglong2 b1 = *(const ulonglong2*)&bbuf[dd * BNC + 64 + tx * 4];
            unsigned long long A[4];
            A[0] = pack2(a0.x); A[1] = pack2(a0.y); A[2] = pack2(a0.z); A[3] = pack2(a0.w);
            #pragma unroll
            for (int m = 0; m < 4; m++) {
                ffma2(acc[m][0], A[m], b0.x);
                ffma2(acc[m][1], A[m], b0.y);
                ffma2(acc[m][2], A[m], b1.x);
                ffma2(acc[m][3], A[m], b1.y);
            }
        }

        if (dk == 7) {
            // dist = c2 - 2*dot ; lexicographic argmin (first-min on ties)
            #pragma unroll
            for (int m = 0; m < 4; m++) {
                #pragma unroll
                for (int p = 0; p < 4; p++) {
                    float2 dv = unpack2(acc[m][p]);
                    int cl = (p < 2) ? (tx * 4 + 2 * p) : (64 + tx * 4 + 2 * (p - 2));
                    int cg0 = cc * BNC + cl;
                    float d0 = fmaf(-2.f, dv.x, __ldg(&c2p[cg0]));
                    float d1 = fmaf(-2.f, dv.y, __ldg(&c2p[cg0 + 1]));
                    if (d0 < bestd[m] || (d0 == bestd[m] && cg0 < bestc[m])) { bestd[m] = d0; bestc[m] = cg0; }
                    if (d1 < bestd[m] || (d1 == bestd[m] && cg0 + 1 < bestc[m])) { bestd[m] = d1; bestc[m] = cg0 + 1; }
                }
            }
        }

        // prefetch chunk i+2 (safe: all warps passed this iteration's barrier,
        // so everyone is done computing from the buffer we overwrite)
        if (i + 2 < NITER) {
            int j = i + 2;
            int jcc = j >> 3, jdk = j & 7;
            uint32_t base = BsAddr + (uint32_t)((j % 3) * (BK * BNC) * 4);
            #pragma unroll
            for (int k = 0; k < 4; k++) {
                int i4 = t + k * NTHREADS;
                int dd = i4 >> 5, c4 = i4 & 31;
                cpasync16(base + (dd * BNC + c4 * 4) * 4,
                          &cbT[(size_t)(jdk * BK + dd) * KK + jcc * BNC + c4 * 4]);
            }
            cpcommit();
        }
    }

    // ---- cross-thread argmin: the 16 threads sharing a row are 16 contiguous lanes ----
    #pragma unroll
    for (int m = 0; m < 4; m++) {
        float d = bestd[m]; int c = bestc[m];
        #pragma unroll
        for (int o = 8; o; o >>= 1) {
            float od = __shfl_xor_sync(0xffffffffu, d, o);
            int   oc = __shfl_xor_sync(0xffffffffu, c, o);
            if (od < d || (od == d && oc < c)) { d = od; c = oc; }
        }
        if (tx == 0) {
            int row = ty * 4 + m;
            codes_sm[row] = c;
            if (writeCodes) outCodes[(rowBase + row) * NQ + s] = (float)c;
        }
    }
    __syncthreads();

    // ---- residual update: g_resT[d][rowBase+r] = Rs[d][r] - cbT[d][code_r] ----
    for (int i = t; i < DD * BM; i += NTHREADS) {
        int d = i >> 6, r = i & 63;
        int code = codes_sm[r];
        g_resT[(size_t)d * NTOT + rowBase + r] = Rs[d * BM + r] - cbT[(size_t)d * KK + code];
    }
}

// ---------------- finalize: quantised[n][d] = x[n][d] - resT[d][n] ----------------
__global__ void finalize_k(const float* __restrict__ x, float* __restrict__ out) {
    __shared__ float tile[32][33];
    int n0 = blockIdx.x * 32, d0 = blockIdx.y * 32;
    int tx = threadIdx.x, ty = threadIdx.y;   // 32 x 8
    #pragma unroll
    for (int i = 0; i < 32; i += 8)
        tile[ty + i][tx] = g_resT[(size_t)(d0 + ty + i) * NTOT + n0 + tx];
    __syncthreads();
    #pragma unroll
    for (int i = 0; i < 32; i += 8) {
        long n = n0 + ty + i;
        int  d = d0 + tx;
        out[n * DD + d] = x[n * DD + d] - tile[tx][ty + i];
    }
}

// ---------------- launch ----------------
extern "C" void kernel_launch(void* const* d_in, const int* in_sizes, int n_in,
                              void* d_out, int out_size) {
    const float* x  = (const float*)d_in[0];
    const float* cb = (const float*)d_in[1];
    float* out = (float*)d_out;

    const long QE = (long)NTOT * DD;
    const long CE = (long)NTOT * NQ;

    int writeQ = (out_size >= QE) ? 1 : 0;
    float* outCodes = nullptr;
    int writeCodes = 0;
    if ((long)out_size >= QE + CE) { outCodes = out + QE; writeCodes = 1; }
    else if (!writeQ && (long)out_size >= CE) { outCodes = out; writeCodes = 1; }

    const int SMEM = (DD * BM + 3 * BK * BNC) * 4 + BM * 4;   // 112.25 KB
    cudaFuncSetAttribute(rvq_stage_k, cudaFuncAttributeMaxDynamicSharedMemorySize, SMEM);

    float* cbT_ptr = nullptr;
    cudaGetSymbolAddress((void**)&cbT_ptr, g_cbT);
    float* resT_ptr = nullptr;
    cudaGetSymbolAddress((void**)&resT_ptr, g_resT);

    dim3 tb(32, 8);
    transpose_k<<<dim3(DD / 32, KK / 32, NQ), tb>>>(cb, cbT_ptr, KK, DD,
                                                    (long)KK * DD, (long)DD * KK);
    transpose_k<<<dim3(DD / 32, NTOT / 32, 1), tb>>>(x, resT_ptr, NTOT, DD, 0, 0);
    c2_k<<<(NQ * KK * 32 + 255) / 256, 256>>>(cb);

    for (int s = 0; s < NQ; s++)
        rvq_stage_k<<<NTOT / BM, NTHREADS, SMEM>>>(s, outCodes, writeCodes);

    if (writeQ)
        finalize_k<<<dim3(NTOT / 32, DD / 32), tb>>>(x, out);
}